// round 6
// baseline (speedup 1.0000x reference)
#include <cuda_runtime.h>
#include <cuda_bf16.h>
#include <cuda_fp16.h>
#include <cuda_fp8.h>
#include <cstdint>
#include <cstddef>

// ---------------- problem constants ----------------
#define H_DIM   2048
#define V_DIM   32000
#define NROWS   2048            // B*T rows per model
#define BM      128
#define BN      128
#define BKB     128             // K-chunk in BYTES (=128 fp8 elems)
#define NTILES  250             // 32000 / 128
#define MGROUPS 16              // 2048 / 128
#define NSPLIT  9               // 2*16*9 = 288 CTAs (occ 2, one wave)
#define KCH     16              // K-chunks per n-tile (2048/128)
#define THREADS 256
#define L2E     1.4426950408889634f
#define LN2     0.6931471805599453f
#define WSCALE  64.0f
#define INVSC   (1.0f / 64.0f)

// ---------------- SMEM ----------------
#define A_BYTES (BM * 128)              // 16384
#define B_BYTES (BN * 128)              // 16384
#define BUF_B   (A_BYTES + B_BYTES)     // 32768
#define SMEM_TOTAL (3 * BUF_B)          // 98304 -> 2 CTAs/SM

// ---------------- device scratch ----------------
__device__ uint8_t g_W8[2][(size_t)V_DIM * H_DIM];   // e4m3, W*64
__device__ uint8_t g_x8[2][(size_t)NROWS * H_DIM];   // e4m3, x*log2(e)
__device__ float2 g_part[2 * NROWS * NSPLIT * 2];
__device__ float  g_logp[2 * NROWS];
__device__ float  g_maskf[2 * NROWS];
__device__ int    g_y64;

// ---------------- helpers ----------------
__device__ __forceinline__ uint32_t smem_u32(const void* p) {
    uint32_t a;
    asm("{ .reg .u64 t; cvta.to.shared.u64 t, %1; cvt.u32.u64 %0, t; }"
        : "=r"(a) : "l"(p));
    return a;
}

#define SW128(o) ((o) ^ (((o) >> 3) & 0x70))

__device__ __forceinline__ void cp_async16(uint32_t saddr, const void* gaddr) {
    asm volatile("cp.async.cg.shared.global [%0], [%1], 16;"
                 :: "r"(saddr), "l"(gaddr) : "memory");
}
#define CP_COMMIT() asm volatile("cp.async.commit_group;" ::: "memory")
template<int N> __device__ __forceinline__ void cp_wait() {
    asm volatile("cp.async.wait_group %0;" :: "n"(N) : "memory");
}

__device__ __forceinline__ void ldsm_x4(uint32_t (&r)[4], uint32_t addr) {
    asm volatile("ldmatrix.sync.aligned.m8n8.x4.shared.b16 {%0,%1,%2,%3}, [%4];"
        : "=r"(r[0]), "=r"(r[1]), "=r"(r[2]), "=r"(r[3]) : "r"(addr));
}

// fp8 e4m3 MMA: D(16x8,f32) += A(16x32) * B(32x8)
__device__ __forceinline__ void mma16832(float (&d)[4], const uint32_t (&a)[4],
                                         uint32_t b0, uint32_t b1) {
    asm volatile(
        "mma.sync.aligned.m16n8k32.row.col.f32.e4m3.e4m3.f32 "
        "{%0,%1,%2,%3}, {%4,%5,%6,%7}, {%8,%9}, {%0,%1,%2,%3};"
        : "+f"(d[0]), "+f"(d[1]), "+f"(d[2]), "+f"(d[3])
        : "r"(a[0]), "r"(a[1]), "r"(a[2]), "r"(a[3]), "r"(b0), "r"(b1));
}

// ---------------- fp32 -> e4m3 conversion ----------------
__global__ void cvt8_kernel(const float* __restrict__ src, int isW, int model,
                            int n4, float scale) {
    int i = blockIdx.x * blockDim.x + threadIdx.x;
    if (i >= n4) return;
    uint8_t* dst = isW ? g_W8[model] : g_x8[model];
    float4 v = reinterpret_cast<const float4*>(src)[i];
    __nv_fp8_e4m3 b0(v.x * scale), b1(v.y * scale), b2(v.z * scale), b3(v.w * scale);
    uchar4 o;
    o.x = b0.__x; o.y = b1.__x; o.z = b2.__x; o.w = b3.__x;
    reinterpret_cast<uchar4*>(dst)[i] = o;
}

// ---------------- y dtype detect (int32 vs int64) ----------------
__global__ void detect_kernel(const int* __restrict__ y32) {
    if (threadIdx.x == 0) {
        int z = 0;
        for (int i = 0; i < 32; i++)
            if (y32[2 * i + 1] == 0) z++;
        g_y64 = (z >= 28) ? 1 : 0;
    }
}

// ---------------- chunk loader: A (128x128B) + B (128x128B) fp8 -------
__device__ __forceinline__ void load_chunk(
    uint32_t dstbase,
    const uint8_t* __restrict__ xrows,
    const uint8_t* __restrict__ Wb,
    int nt, int kc, int tid)
{
    #pragma unroll
    for (int j = 0; j < 4; j++) {                 // A: 1024 x 16B segs
        int idx = j * THREADS + tid;
        int row = idx >> 3, seg = idx & 7;
        uint32_t sa = dstbase + SW128((uint32_t)(row * 128 + seg * 16));
        cp_async16(sa, xrows + (size_t)row * H_DIM + kc * BKB + seg * 16);
    }
    #pragma unroll
    for (int j = 0; j < 4; j++) {                 // B: 1024 x 16B segs
        int idx = j * THREADS + tid;
        int row = idx >> 3, seg = idx & 7;
        uint32_t sa = dstbase + A_BYTES + SW128((uint32_t)(row * 128 + seg * 16));
        cp_async16(sa, Wb + (size_t)(nt * BN + row) * H_DIM + kc * BKB + seg * 16);
    }
    CP_COMMIT();
}

// ---------------- main fused FP8 GEMM + online LSE (log2 domain) ------
__global__ void __launch_bounds__(THREADS, 2) dpo_main_kernel() {
    extern __shared__ char smem[];
    const uint32_t sb = smem_u32(smem);
    const int tid = threadIdx.x;
    const int lid = tid & 31;
    const int wid = tid >> 5;
    const int wm  = wid >> 1;       // 0..3 (M position, 32 rows each)
    const int wn  = wid & 1;        // 0..1 (N position, 64 cols each)

    const int cta    = blockIdx.x;
    const int model  = cta / (MGROUPS * NSPLIT);
    const int rest   = cta % (MGROUPS * NSPLIT);
    const int mgroup = rest / NSPLIT;
    const int split  = rest % NSPLIT;

    const uint8_t* __restrict__ Wb = g_W8[model];
    const uint8_t* __restrict__ xrows =
        g_x8[model] + (size_t)(mgroup * BM) * H_DIM;

    const int ntcount = (NTILES - split + NSPLIT - 1) / NSPLIT;
    const int total   = ntcount * KCH;

    // swizzled base offsets (identical pattern to bf16 version; byte-exact)
    const int a_row0 = wm * 32 + (lid & 15);
    const uint32_t a_kh = (uint32_t)((lid >> 4) * 16);
    const int b_row0 = wn * 64 + (lid & 7) + ((lid >> 4) << 3);
    const uint32_t b_kh = (uint32_t)(((lid >> 3) & 1) * 16);

    uint32_t a_off[2], b_off[4];
    #pragma unroll
    for (int i = 0; i < 2; i++)
        a_off[i] = SW128((uint32_t)((a_row0 + i * 16) * 128) + a_kh);
    #pragma unroll
    for (int j = 0; j < 4; j++)
        b_off[j] = SW128((uint32_t)((b_row0 + j * 16) * 128) + b_kh) + A_BYTES;

    float acc[2][8][4];
    #pragma unroll
    for (int i = 0; i < 2; i++)
        #pragma unroll
        for (int j = 0; j < 8; j++)
            #pragma unroll
            for (int q = 0; q < 4; q++) acc[i][j][q] = 0.f;

    float run_m[4], run_s[4];
    #pragma unroll
    for (int q = 0; q < 4; q++) { run_m[q] = -3.0e38f; run_s[q] = 0.f; }

    load_chunk(sb + 0 * BUF_B, xrows, Wb, split, 0, tid);
    if (total > 1)
        load_chunk(sb + 1 * BUF_B, xrows, Wb, split, 1, tid);

    #pragma unroll 1
    for (int c = 0; c < total; c++) {
        if (c + 2 < total) cp_wait<1>(); else cp_wait<0>();
        __syncthreads();

        // prefetch chunk c+2 (its buffer was consumed at c-1; safe post-barrier)
        if (c + 2 < total) {
            int c2 = c + 2;
            load_chunk(sb + (c2 % 3) * BUF_B, xrows, Wb,
                       split + NSPLIT * (c2 >> 4), c2 & 15, tid);
        }

        const uint32_t bufbase = sb + (c % 3) * BUF_B;
        #pragma unroll
        for (int ks = 0; ks < 4; ks++) {          // 4 x K=32 fp8
            const uint32_t kx = (uint32_t)(ks << 5);
            uint32_t a_frag[2][4];
            ldsm_x4(a_frag[0], (bufbase + a_off[0]) ^ kx);
            ldsm_x4(a_frag[1], (bufbase + a_off[1]) ^ kx);
            uint32_t bcur[4], bnext[4];
            ldsm_x4(bcur, (bufbase + b_off[0]) ^ kx);
            #pragma unroll
            for (int j2 = 0; j2 < 4; j2++) {
                if (j2 < 3) ldsm_x4(bnext, (bufbase + b_off[j2 + 1]) ^ kx);
                #pragma unroll
                for (int i = 0; i < 2; i++) {
                    mma16832(acc[i][j2 * 2],     a_frag[i], bcur[0], bcur[1]);
                    mma16832(acc[i][j2 * 2 + 1], a_frag[i], bcur[2], bcur[3]);
                }
                #pragma unroll
                for (int q = 0; q < 4; q++) bcur[q] = bnext[q];
            }
        }

        if ((c & (KCH - 1)) == (KCH - 1)) {
            // epilogue: online max / sum-exp2; true logit2 = acc * INVSC
            #pragma unroll
            for (int i = 0; i < 2; i++) {
                #pragma unroll
                for (int rh = 0; rh < 2; rh++) {
                    const int rr = i * 2 + rh;
                    float rmax = -3.0e38f;
                    #pragma unroll
                    for (int j = 0; j < 8; j++)
                        rmax = fmaxf(rmax, fmaxf(acc[i][j][rh * 2],
                                                 acc[i][j][rh * 2 + 1]));
                    rmax *= INVSC;
                    rmax = fmaxf(rmax, __shfl_xor_sync(0xffffffffu, rmax, 1));
                    rmax = fmaxf(rmax, __shfl_xor_sync(0xffffffffu, rmax, 2));
                    const float mnew = fmaxf(run_m[rr], rmax);
                    __half2 s2 = __float2half2_rn(0.f);
                    #pragma unroll
                    for (int j = 0; j < 8; j++) {
                        float d0 = fmaf(acc[i][j][rh * 2],     INVSC, -mnew);
                        float d1 = fmaf(acc[i][j][rh * 2 + 1], INVSC, -mnew);
                        s2 = __hadd2(s2, h2exp2(__floats2half2_rn(d0, d1)));
                    }
                    float2 sf = __half22float2(s2);
                    float st = sf.x + sf.y;
                    st += __shfl_xor_sync(0xffffffffu, st, 1);
                    st += __shfl_xor_sync(0xffffffffu, st, 2);
                    run_s[rr] = run_s[rr] * exp2f(run_m[rr] - mnew) + st;
                    run_m[rr] = mnew;
                }
            }
            #pragma unroll
            for (int i = 0; i < 2; i++)
                #pragma unroll
                for (int j = 0; j < 8; j++)
                    #pragma unroll
                    for (int q = 0; q < 4; q++) acc[i][j][q] = 0.f;
        }
    }

    // write per-(row, split*2+wn) partials
    if ((lid & 3) == 0) {
        #pragma unroll
        for (int i = 0; i < 2; i++)
            #pragma unroll
            for (int rh = 0; rh < 2; rh++) {
                int grow = mgroup * BM + wm * 32 + i * 16 + rh * 8 + (lid >> 2);
                g_part[((size_t)(model * NROWS + grow) * NSPLIT + split) * 2 + wn] =
                    make_float2(run_m[i * 2 + rh], run_s[i * 2 + rh]);
            }
    }
}

// ---------------- combine partials + exact fp32 token dot ------------
__global__ void reduce_kernel(const void* __restrict__ yp,
                              const float* __restrict__ x,
                              const float* __restrict__ rx,
                              const float* __restrict__ W,
                              const float* __restrict__ rW) {
    int wid = threadIdx.x >> 5, lid = threadIdx.x & 31;
    int row_all = blockIdx.x * 8 + wid;
    if (row_all >= 2 * NROWS) return;
    int model = row_all >> 11;
    int r     = row_all & (NROWS - 1);

    long long yv = g_y64 ? ((const long long*)yp)[r]
                         : (long long)((const int*)yp)[r];
    bool mask = (yv != -100);
    int safe = mask ? (int)yv : 0;

    // exact token logit from ORIGINAL fp32 inputs
    const float4* xr = (const float4*)((model ? rx : x) + (size_t)r * H_DIM);
    const float4* wr = (const float4*)((model ? rW : W) + (size_t)safe * H_DIM);
    float acc = 0.f;
    #pragma unroll 4
    for (int t = 0; t < 16; t++) {
        int i = t * 32 + lid;
        float4 a = xr[i];
        float4 b = wr[i];
        acc = fmaf(a.x, b.x, acc);
        acc = fmaf(a.y, b.y, acc);
        acc = fmaf(a.z, b.z, acc);
        acc = fmaf(a.w, b.w, acc);
    }
    #pragma unroll
    for (int off = 16; off; off >>= 1)
        acc += __shfl_xor_sync(0xffffffffu, acc, off);

    const float2* pp = &g_part[(size_t)(model * NROWS + r) * NSPLIT * 2];
    float M = -3.0e38f;
    #pragma unroll
    for (int s = 0; s < NSPLIT * 2; s++) M = fmaxf(M, pp[s].x);
    float S = 0.f;
    #pragma unroll
    for (int s = 0; s < NSPLIT * 2; s++) S += pp[s].y * exp2f(pp[s].x - M);
    float lse_nat = LN2 * (M + log2f(S));       // natural-log LSE
    if (lid == 0) {
        g_logp[row_all]  = mask ? (acc - lse_nat) : 0.f;
        g_maskf[row_all] = mask ? 1.f : 0.f;
    }
}

// ---------------- final loss ----------------
__global__ void final_kernel(float* __restrict__ out) {
    __shared__ float avg[8];
    int wid = threadIdx.x >> 5, lid = threadIdx.x & 31;
    float sl = 0.f, sm = 0.f;
    for (int i = lid; i < 512; i += 32) {
        sl += g_logp[wid * 512 + i];
        sm += g_maskf[wid * 512 + i];
    }
    #pragma unroll
    for (int off = 16; off; off >>= 1) {
        sl += __shfl_xor_sync(0xffffffffu, sl, off);
        sm += __shfl_xor_sync(0xffffffffu, sm, off);
    }
    if (lid == 0) avg[wid] = (sm > 0.f) ? (sl / sm) : 0.f;
    __syncthreads();
    if (threadIdx.x == 0) {
        const float BETA = 0.1f;
        float loss = 0.f;
        for (int b = 0; b < 4; b++) {
            float lr = avg[b] - avg[4 + b];
            float z = (b < 2) ? (BETA * lr) : (-BETA * lr);
            float sig = 1.f / (1.f + expf(-z));
            loss += 1.f - sig;
        }
        out[0] = loss / 2.f;
    }
}

// ---------------- launcher ----------------
extern "C" void kernel_launch(void* const* d_in, const int* in_sizes, int n_in,
                              void* d_out, int out_size) {
    const float* x  = (const float*)d_in[0];
    const float* rx = (const float*)d_in[1];
    const void*  y  = d_in[2];
    const float* W  = (const float*)d_in[3];
    const float* rW = (const float*)d_in[4];
    float* out = (float*)d_out;

    cudaFuncSetAttribute(dpo_main_kernel,
                         cudaFuncAttributeMaxDynamicSharedMemorySize, SMEM_TOTAL);

    cvt8_kernel<<<4096,  256>>>(x,  0, 0, NROWS * H_DIM / 4, L2E);
    cvt8_kernel<<<4096,  256>>>(rx, 0, 1, NROWS * H_DIM / 4, L2E);
    cvt8_kernel<<<64000, 256>>>(W,  1, 0, V_DIM * H_DIM / 4, WSCALE);
    cvt8_kernel<<<64000, 256>>>(rW, 1, 1, V_DIM * H_DIM / 4, WSCALE);
    detect_kernel<<<1, 32>>>((const int*)y);
    dpo_main_kernel<<<2 * MGROUPS * NSPLIT, THREADS, SMEM_TOTAL>>>();
    reduce_kernel<<<512, 256>>>(y, x, rx, W, rW);
    final_kernel<<<1, 256>>>(out);
}

// round 7
// speedup vs baseline: 1.2121x; 1.2121x over previous
#include <cuda_runtime.h>
#include <cuda_bf16.h>
#include <cuda_fp16.h>
#include <cstdint>
#include <cstddef>

// ---------------- problem constants ----------------
#define H_DIM   2048
#define V_DIM   32000
#define NROWS   2048            // B*T rows per model
#define BM      128
#define BN      128
#define BK      64
#define NTILES  250             // 32000 / 128
#define MGROUPS 16              // 2048 / 128
#define NSPLIT  9               // 2*16*9 = 288 CTAs (occ 2, one wave)
#define KCH     32              // K-chunks per n-tile
#define THREADS 256
#define L2E     1.4426950408889634f
#define LN2     0.6931471805599453f

// ---------------- SMEM ----------------
#define A_BYTES (BM * 128)              // 16384
#define B_BYTES (BN * 128)              // 16384
#define BUF_B   (A_BYTES + B_BYTES)     // 32768
#define SMEM_DATA 1024
#define SMEM_TOTAL (SMEM_DATA + 3 * BUF_B)   // 99328 -> 2 CTAs/SM

// ---------------- device scratch ----------------
__device__ __nv_bfloat16 g_Wb[2][(size_t)V_DIM * H_DIM];
__device__ __nv_bfloat16 g_xb[2][(size_t)NROWS * H_DIM];  // pre-scaled by log2(e)
__device__ float2 g_part[2 * NROWS * NSPLIT * 2];
__device__ float  g_logp[2 * NROWS];
__device__ float  g_maskf[2 * NROWS];
__device__ int    g_y64;

// ---------------- helpers ----------------
__device__ __forceinline__ uint32_t smem_u32(const void* p) {
    uint32_t a;
    asm("{ .reg .u64 t; cvta.to.shared.u64 t, %1; cvt.u32.u64 %0, t; }"
        : "=r"(a) : "l"(p));
    return a;
}

#define SW128(o) ((o) ^ (((o) >> 3) & 0x70))

__device__ __forceinline__ void cp_async16(uint32_t saddr, const void* gaddr) {
    asm volatile("cp.async.cg.shared.global [%0], [%1], 16;"
                 :: "r"(saddr), "l"(gaddr) : "memory");
}

// cp.async completion -> mbarrier arrival (one per thread, count not bumped)
__device__ __forceinline__ void cp_async_mbar_arrive(uint32_t mbar) {
    asm volatile("cp.async.mbarrier.arrive.noinc.shared.b64 [%0];"
                 :: "r"(mbar) : "memory");
}

#define MBARRIER_INIT(addr, cnt) \
    asm volatile("mbarrier.init.shared.b64 [%0], %1;" \
        :: "r"((uint32_t)(addr)), "r"((uint32_t)(cnt)) : "memory")

#define MBARRIER_ARRIVE(addr) \
    asm volatile("mbarrier.arrive.shared.b64 _, [%0];" \
        :: "r"((uint32_t)(addr)) : "memory")

#define MBARRIER_WAIT_PARITY(addr, par) do {                                   \
    uint32_t _mb = (uint32_t)(addr); uint32_t _pp = (uint32_t)(par);           \
    uint32_t _done;                                                            \
    asm volatile("{\n\t.reg .pred p;\n\t"                                      \
        "mbarrier.try_wait.parity.acquire.cta.shared::cta.b64 p, [%1], %2;\n\t"\
        "selp.b32 %0, 1, 0, p;\n\t}"                                           \
        : "=r"(_done) : "r"(_mb), "r"(_pp) : "memory");                        \
    if (!_done) {                                                              \
        asm volatile("{\n\t.reg .pred P1;\n\t"                                 \
            "WAIT_LOOP_%=:\n\t"                                                \
            "mbarrier.try_wait.parity.acquire.cta.shared::cta.b64 P1, [%0], %1, 0x989680;\n\t" \
            "@P1 bra.uni WAIT_DONE_%=;\n\t"                                    \
            "bra.uni WAIT_LOOP_%=;\n\t"                                        \
            "WAIT_DONE_%=:\n\t}"                                               \
            :: "r"(_mb), "r"(_pp) : "memory");                                 \
    }                                                                          \
} while (0)

__device__ __forceinline__ void ldsm_x4(uint32_t (&r)[4], uint32_t addr) {
    asm volatile("ldmatrix.sync.aligned.m8n8.x4.shared.b16 {%0,%1,%2,%3}, [%4];"
        : "=r"(r[0]), "=r"(r[1]), "=r"(r[2]), "=r"(r[3]) : "r"(addr));
}

__device__ __forceinline__ void mma16816(float (&d)[4], const uint32_t (&a)[4],
                                         uint32_t b0, uint32_t b1) {
    asm volatile(
        "mma.sync.aligned.m16n8k16.row.col.f32.bf16.bf16.f32 "
        "{%0,%1,%2,%3}, {%4,%5,%6,%7}, {%8,%9}, {%0,%1,%2,%3};"
        : "+f"(d[0]), "+f"(d[1]), "+f"(d[2]), "+f"(d[3])
        : "r"(a[0]), "r"(a[1]), "r"(a[2]), "r"(a[3]), "r"(b0), "r"(b1));
}

// ---------------- fp32 -> bf16 conversion (x gets log2(e) scale) ----------
__global__ void cvt_kernel(const float* __restrict__ src, int isW, int model,
                           int n4, float scale) {
    int i = blockIdx.x * blockDim.x + threadIdx.x;
    if (i >= n4) return;
    __nv_bfloat16* dst = isW ? g_Wb[model] : g_xb[model];
    float4 v = reinterpret_cast<const float4*>(src)[i];
    __nv_bfloat162 lo = __floats2bfloat162_rn(v.x * scale, v.y * scale);
    __nv_bfloat162 hi = __floats2bfloat162_rn(v.z * scale, v.w * scale);
    uint2 o;
    o.x = *reinterpret_cast<unsigned*>(&lo);
    o.y = *reinterpret_cast<unsigned*>(&hi);
    reinterpret_cast<uint2*>(dst)[i] = o;
}

// ---------------- y dtype detect (int32 vs int64) ----------------
__global__ void detect_kernel(const int* __restrict__ y32) {
    if (threadIdx.x == 0) {
        int z = 0;
        for (int i = 0; i < 32; i++)
            if (y32[2 * i + 1] == 0) z++;
        g_y64 = (z >= 28) ? 1 : 0;
    }
}

// ---------------- chunk loader: A (128x64) + B (128x64) bf16 ----------
__device__ __forceinline__ void load_chunk(
    uint32_t dstbase,
    const __nv_bfloat16* __restrict__ xrows,
    const __nv_bfloat16* __restrict__ Wb,
    int nt, int kc, int tid)
{
    #pragma unroll
    for (int j = 0; j < 4; j++) {                 // A: 1024 x 16B segs
        int idx = j * THREADS + tid;
        int row = idx >> 3, seg = idx & 7;
        uint32_t sa = dstbase + SW128((uint32_t)(row * 128 + seg * 16));
        cp_async16(sa, xrows + (size_t)row * H_DIM + kc * BK + seg * 8);
    }
    #pragma unroll
    for (int j = 0; j < 4; j++) {                 // B: 1024 x 16B segs
        int idx = j * THREADS + tid;
        int row = idx >> 3, seg = idx & 7;
        uint32_t sa = dstbase + A_BYTES + SW128((uint32_t)(row * 128 + seg * 16));
        cp_async16(sa, Wb + (size_t)(nt * BN + row) * H_DIM + kc * BK + seg * 8);
    }
}

// ---------------- main fused GEMM + online LSE (log2 domain) ----------
__global__ void __launch_bounds__(THREADS, 2) dpo_main_kernel() {
    extern __shared__ char smem[];
    const uint32_t sb = smem_u32(smem);
    const int tid = threadIdx.x;
    const int lid = tid & 31;
    const int wid = tid >> 5;
    const int wm  = wid >> 1;       // 0..3 (M position, 32 rows each)
    const int wn  = wid & 1;        // 0..1 (N position, 64 cols each)

    // mbarriers: full[b] at sb + b*8, empty[b] at sb + 24 + b*8
    const uint32_t mb_full0  = sb;
    const uint32_t mb_empty0 = sb + 24;

    const int cta    = blockIdx.x;
    const int model  = cta / (MGROUPS * NSPLIT);
    const int rest   = cta % (MGROUPS * NSPLIT);
    const int mgroup = rest / NSPLIT;
    const int split  = rest % NSPLIT;

    const __nv_bfloat16* __restrict__ Wb = g_Wb[model];
    const __nv_bfloat16* __restrict__ xrows =
        g_xb[model] + (size_t)(mgroup * BM) * H_DIM;

    const int ntcount = (NTILES - split + NSPLIT - 1) / NSPLIT;
    const int total   = ntcount * KCH;

    if (tid == 0) {
        #pragma unroll
        for (int b = 0; b < 3; b++) {
            MBARRIER_INIT(mb_full0  + b * 8, THREADS);
            MBARRIER_INIT(mb_empty0 + b * 8, THREADS);
        }
    }
    __syncthreads();

    // swizzled base offsets (relative to buffer base)
    const int a_row0 = wm * 32 + (lid & 15);
    const uint32_t a_kh = (uint32_t)((lid >> 4) * 16);
    const int b_row0 = wn * 64 + (lid & 7) + ((lid >> 4) << 3);
    const uint32_t b_kh = (uint32_t)(((lid >> 3) & 1) * 16);

    uint32_t a_off[2], b_off[4];
    #pragma unroll
    for (int i = 0; i < 2; i++)
        a_off[i] = SW128((uint32_t)((a_row0 + i * 16) * 128) + a_kh);
    #pragma unroll
    for (int j = 0; j < 4; j++)
        b_off[j] = SW128((uint32_t)((b_row0 + j * 16) * 128) + b_kh) + A_BYTES;

    float acc[2][8][4];
    #pragma unroll
    for (int i = 0; i < 2; i++)
        #pragma unroll
        for (int j = 0; j < 8; j++)
            #pragma unroll
            for (int q = 0; q < 4; q++) acc[i][j][q] = 0.f;

    float run_m[4], run_s[4];
    #pragma unroll
    for (int q = 0; q < 4; q++) { run_m[q] = -3.0e38f; run_s[q] = 0.f; }

    // prologue: fill buffers 0, 1 (chunks 0, 1)
    load_chunk(sb + SMEM_DATA + 0 * BUF_B, xrows, Wb, split, 0, tid);
    cp_async_mbar_arrive(mb_full0 + 0 * 8);
    load_chunk(sb + SMEM_DATA + 1 * BUF_B, xrows, Wb, split, 1, tid);
    cp_async_mbar_arrive(mb_full0 + 1 * 8);

    #pragma unroll 1
    for (int c = 0; c < total; c++) {
        const int b  = c % 3;

        // producer: fill buffer (c+2)%3 with chunk c+2
        if (c + 2 < total) {
            const int b2 = (c + 2) % 3;
            if (c >= 1)   // wait readers of chunk c-1 (same buffer) done
                MBARRIER_WAIT_PARITY(mb_empty0 + b2 * 8, ((c - 1) / 3) & 1);
            const int c2 = c + 2;
            load_chunk(sb + SMEM_DATA + b2 * BUF_B, xrows, Wb,
                       split + NSPLIT * (c2 >> 5), c2 & 31, tid);
            cp_async_mbar_arrive(mb_full0 + b2 * 8);
        }

        // consumer: wait chunk c data
        MBARRIER_WAIT_PARITY(mb_full0 + b * 8, (c / 3) & 1);

        const uint32_t bufbase = sb + SMEM_DATA + b * BUF_B;
        #pragma unroll
        for (int ks = 0; ks < 4; ks++) {
            const uint32_t kx = (uint32_t)(ks << 5);
            uint32_t a_frag[2][4], b_frag[4][4];
            ldsm_x4(a_frag[0], (bufbase + a_off[0]) ^ kx);
            ldsm_x4(a_frag[1], (bufbase + a_off[1]) ^ kx);
            #pragma unroll
            for (int j2 = 0; j2 < 4; j2++)
                ldsm_x4(b_frag[j2], (bufbase + b_off[j2]) ^ kx);
            #pragma unroll
            for (int j2 = 0; j2 < 4; j2++)
                #pragma unroll
                for (int i = 0; i < 2; i++) {
                    mma16816(acc[i][j2 * 2],     a_frag[i], b_frag[j2][0], b_frag[j2][1]);
                    mma16816(acc[i][j2 * 2 + 1], a_frag[i], b_frag[j2][2], b_frag[j2][3]);
                }
        }

        // done reading buffer b
        MBARRIER_ARRIVE(mb_empty0 + b * 8);

        if ((c & 31) == 31) {
            // epilogue: online max / sum-exp2 for this n-tile (128 cols)
            #pragma unroll
            for (int i = 0; i < 2; i++) {
                #pragma unroll
                for (int rh = 0; rh < 2; rh++) {
                    const int rr = i * 2 + rh;
                    float rmax = -3.0e38f;
                    #pragma unroll
                    for (int j = 0; j < 8; j++)
                        rmax = fmaxf(rmax, fmaxf(acc[i][j][rh * 2],
                                                 acc[i][j][rh * 2 + 1]));
                    rmax = fmaxf(rmax, __shfl_xor_sync(0xffffffffu, rmax, 1));
                    rmax = fmaxf(rmax, __shfl_xor_sync(0xffffffffu, rmax, 2));
                    const float mnew = fmaxf(run_m[rr], rmax);
                    __half2 s2 = __float2half2_rn(0.f);
                    #pragma unroll
                    for (int j = 0; j < 8; j++) {
                        float d0 = acc[i][j][rh * 2]     - mnew;
                        float d1 = acc[i][j][rh * 2 + 1] - mnew;
                        s2 = __hadd2(s2, h2exp2(__floats2half2_rn(d0, d1)));
                    }
                    float2 sf = __half22float2(s2);
                    float st = sf.x + sf.y;
                    st += __shfl_xor_sync(0xffffffffu, st, 1);
                    st += __shfl_xor_sync(0xffffffffu, st, 2);
                    run_s[rr] = run_s[rr] * exp2f(run_m[rr] - mnew) + st;
                    run_m[rr] = mnew;
                }
            }
            #pragma unroll
            for (int i = 0; i < 2; i++)
                #pragma unroll
                for (int j = 0; j < 8; j++)
                    #pragma unroll
                    for (int q = 0; q < 4; q++) acc[i][j][q] = 0.f;
        }
    }

    // write per-(row, split*2+wn) partials
    if ((lid & 3) == 0) {
        #pragma unroll
        for (int i = 0; i < 2; i++)
            #pragma unroll
            for (int rh = 0; rh < 2; rh++) {
                int grow = mgroup * BM + wm * 32 + i * 16 + rh * 8 + (lid >> 2);
                g_part[((size_t)(model * NROWS + grow) * NSPLIT + split) * 2 + wn] =
                    make_float2(run_m[i * 2 + rh], run_s[i * 2 + rh]);
            }
    }
}

// ---------------- combine partials + exact fp32 token dot ------------
__global__ void reduce_kernel(const void* __restrict__ yp,
                              const float* __restrict__ x,
                              const float* __restrict__ rx,
                              const float* __restrict__ W,
                              const float* __restrict__ rW) {
    int wid = threadIdx.x >> 5, lid = threadIdx.x & 31;
    int row_all = blockIdx.x * 8 + wid;
    if (row_all >= 2 * NROWS) return;
    int model = row_all >> 11;
    int r     = row_all & (NROWS - 1);

    long long yv = g_y64 ? ((const long long*)yp)[r]
                         : (long long)((const int*)yp)[r];
    bool mask = (yv != -100);
    int safe = mask ? (int)yv : 0;

    // exact token logit from ORIGINAL fp32 inputs (natural units)
    const float4* xr = (const float4*)((model ? rx : x) + (size_t)r * H_DIM);
    const float4* wr = (const float4*)((model ? rW : W) + (size_t)safe * H_DIM);
    float acc = 0.f;
    #pragma unroll 4
    for (int t = 0; t < 16; t++) {
        int i = t * 32 + lid;
        float4 a = xr[i];
        float4 b = wr[i];
        acc = fmaf(a.x, b.x, acc);
        acc = fmaf(a.y, b.y, acc);
        acc = fmaf(a.z, b.z, acc);
        acc = fmaf(a.w, b.w, acc);
    }
    #pragma unroll
    for (int off = 16; off; off >>= 1)
        acc += __shfl_xor_sync(0xffffffffu, acc, off);

    const float2* pp = &g_part[(size_t)(model * NROWS + r) * NSPLIT * 2];
    float M = -3.0e38f;
    #pragma unroll
    for (int s = 0; s < NSPLIT * 2; s++) M = fmaxf(M, pp[s].x);
    float S = 0.f;
    #pragma unroll
    for (int s = 0; s < NSPLIT * 2; s++) S += pp[s].y * exp2f(pp[s].x - M);
    float lse_nat = LN2 * (M + log2f(S));   // lse in log2 units -> natural
    if (lid == 0) {
        g_logp[row_all]  = mask ? (acc - lse_nat) : 0.f;
        g_maskf[row_all] = mask ? 1.f : 0.f;
    }
}

// ---------------- final loss ----------------
__global__ void final_kernel(float* __restrict__ out) {
    __shared__ float avg[8];
    int wid = threadIdx.x >> 5, lid = threadIdx.x & 31;
    float sl = 0.f, sm = 0.f;
    for (int i = lid; i < 512; i += 32) {
        sl += g_logp[wid * 512 + i];
        sm += g_maskf[wid * 512 + i];
    }
    #pragma unroll
    for (int off = 16; off; off >>= 1) {
        sl += __shfl_xor_sync(0xffffffffu, sl, off);
        sm += __shfl_xor_sync(0xffffffffu, sm, off);
    }
    if (lid == 0) avg[wid] = (sm > 0.f) ? (sl / sm) : 0.f;
    __syncthreads();
    if (threadIdx.x == 0) {
        const float BETA = 0.1f;
        float loss = 0.f;
        for (int b = 0; b < 4; b++) {
            float lr = avg[b] - avg[4 + b];
            float z = (b < 2) ? (BETA * lr) : (-BETA * lr);
            float sig = 1.f / (1.f + expf(-z));
            loss += 1.f - sig;
        }
        out[0] = loss / 2.f;
    }
}

// ---------------- launcher ----------------
extern "C" void kernel_launch(void* const* d_in, const int* in_sizes, int n_in,
                              void* d_out, int out_size) {
    const float* x  = (const float*)d_in[0];
    const float* rx = (const float*)d_in[1];
    const void*  y  = d_in[2];
    const float* W  = (const float*)d_in[3];
    const float* rW = (const float*)d_in[4];
    float* out = (float*)d_out;

    cudaFuncSetAttribute(dpo_main_kernel,
                         cudaFuncAttributeMaxDynamicSharedMemorySize, SMEM_TOTAL);

    cvt_kernel<<<4096,  256>>>(x,  0, 0, NROWS * H_DIM / 4, L2E);
    cvt_kernel<<<4096,  256>>>(rx, 0, 1, NROWS * H_DIM / 4, L2E);
    cvt_kernel<<<64000, 256>>>(W,  1, 0, V_DIM * H_DIM / 4, 1.0f);
    cvt_kernel<<<64000, 256>>>(rW, 1, 1, V_DIM * H_DIM / 4, 1.0f);
    detect_kernel<<<1, 32>>>((const int*)y);
    dpo_main_kernel<<<2 * MGROUPS * NSPLIT, THREADS, SMEM_TOTAL>>>();
    reduce_kernel<<<512, 256>>>(y, x, rx, W, rW);
    final_kernel<<<1, 256>>>(out);
}

// round 8
// speedup vs baseline: 1.3606x; 1.1225x over previous
#include <cuda_runtime.h>
#include <cuda_bf16.h>
#include <cuda_fp16.h>
#include <cstdint>
#include <cstddef>

// ---------------- problem constants ----------------
#define H_DIM   2048
#define V_DIM   32000
#define NROWS   2048            // B*T rows per model
#define BM      128
#define BN      128
#define BK      64
#define NTILES  250             // 32000 / 128
#define NITEMS  (NTILES * 32)   // 8000 items = (nt, model, mgroup)
#define GRID    296             // 2 * 148 SMs (occ 2)
#define THREADS 256
#define L2E     1.4426950408889634f
#define LN2     0.6931471805599453f

// ---------------- SMEM ----------------
#define A_BYTES (BM * 128)              // 16384
#define B_BYTES (BN * 128)              // 16384
#define BUF_B   (A_BYTES + B_BYTES)     // 32768
#define SMEM_DATA 1024
#define SMEM_TOTAL (SMEM_DATA + 3 * BUF_B)   // 99328 -> 2 CTAs/SM

// ---------------- device scratch ----------------
__device__ __nv_bfloat16 g_Wb[2][(size_t)V_DIM * H_DIM];
__device__ __nv_bfloat16 g_xb[2][(size_t)NROWS * H_DIM];  // pre-scaled by log2(e)
__device__ float2   g_part[(size_t)2 * NROWS * 512];      // [2*NTILES per row]
__device__ float    g_logp[2 * NROWS];
__device__ float    g_maskf[2 * NROWS];
__device__ int      g_y64;
__device__ unsigned g_ticket;

// ---------------- helpers ----------------
__device__ __forceinline__ uint32_t smem_u32(const void* p) {
    uint32_t a;
    asm("{ .reg .u64 t; cvta.to.shared.u64 t, %1; cvt.u32.u64 %0, t; }"
        : "=r"(a) : "l"(p));
    return a;
}

#define SW128(o) ((o) ^ (((o) >> 3) & 0x70))

__device__ __forceinline__ void cp_async16(uint32_t saddr, const void* gaddr) {
    asm volatile("cp.async.cg.shared.global [%0], [%1], 16;"
                 :: "r"(saddr), "l"(gaddr) : "memory");
}

__device__ __forceinline__ void cp_async_mbar_arrive(uint32_t mbar) {
    asm volatile("cp.async.mbarrier.arrive.noinc.shared.b64 [%0];"
                 :: "r"(mbar) : "memory");
}

#define MBARRIER_INIT(addr, cnt) \
    asm volatile("mbarrier.init.shared.b64 [%0], %1;" \
        :: "r"((uint32_t)(addr)), "r"((uint32_t)(cnt)) : "memory")

#define MBARRIER_ARRIVE(addr) \
    asm volatile("mbarrier.arrive.shared.b64 _, [%0];" \
        :: "r"((uint32_t)(addr)) : "memory")

#define MBARRIER_WAIT_PARITY(addr, par) do {                                   \
    uint32_t _mb = (uint32_t)(addr); uint32_t _pp = (uint32_t)(par);           \
    uint32_t _done;                                                            \
    asm volatile("{\n\t.reg .pred p;\n\t"                                      \
        "mbarrier.try_wait.parity.acquire.cta.shared::cta.b64 p, [%1], %2;\n\t"\
        "selp.b32 %0, 1, 0, p;\n\t}"                                           \
        : "=r"(_done) : "r"(_mb), "r"(_pp) : "memory");                        \
    if (!_done) {                                                              \
        asm volatile("{\n\t.reg .pred P1;\n\t"                                 \
            "WAIT_LOOP_%=:\n\t"                                                \
            "mbarrier.try_wait.parity.acquire.cta.shared::cta.b64 P1, [%0], %1, 0x989680;\n\t" \
            "@P1 bra.uni WAIT_DONE_%=;\n\t"                                    \
            "bra.uni WAIT_LOOP_%=;\n\t"                                        \
            "WAIT_DONE_%=:\n\t}"                                               \
            :: "r"(_mb), "r"(_pp) : "memory");                                 \
    }                                                                          \
} while (0)

__device__ __forceinline__ void ldsm_x4(uint32_t (&r)[4], uint32_t addr) {
    asm volatile("ldmatrix.sync.aligned.m8n8.x4.shared.b16 {%0,%1,%2,%3}, [%4];"
        : "=r"(r[0]), "=r"(r[1]), "=r"(r[2]), "=r"(r[3]) : "r"(addr));
}

__device__ __forceinline__ void mma16816(float (&d)[4], const uint32_t (&a)[4],
                                         uint32_t b0, uint32_t b1) {
    asm volatile(
        "mma.sync.aligned.m16n8k16.row.col.f32.bf16.bf16.f32 "
        "{%0,%1,%2,%3}, {%4,%5,%6,%7}, {%8,%9}, {%0,%1,%2,%3};"
        : "+f"(d[0]), "+f"(d[1]), "+f"(d[2]), "+f"(d[3])
        : "r"(a[0]), "r"(a[1]), "r"(a[2]), "r"(a[3]), "r"(b0), "r"(b1));
}

// ---------------- merged fp32 -> bf16 conversion -----------------------
#define WN4 (V_DIM * H_DIM / 4)     // 16,384,000
#define XN4 (NROWS * H_DIM / 4)     // 1,048,576

__global__ void cvt_all_kernel(const float* __restrict__ x,
                               const float* __restrict__ rx,
                               const float* __restrict__ W,
                               const float* __restrict__ rW) {
    int i = blockIdx.x * blockDim.x + threadIdx.x;
    const float* src;
    __nv_bfloat16* dst;
    float scale;
    int off;
    if (i < WN4)                { src = W;  dst = g_Wb[0]; scale = 1.0f; off = i; }
    else if (i < 2 * WN4)       { src = rW; dst = g_Wb[1]; scale = 1.0f; off = i - WN4; }
    else if (i < 2 * WN4 + XN4) { src = x;  dst = g_xb[0]; scale = L2E;  off = i - 2 * WN4; }
    else                        { src = rx; dst = g_xb[1]; scale = L2E;  off = i - 2 * WN4 - XN4; }
    float4 v = reinterpret_cast<const float4*>(src)[off];
    __nv_bfloat162 lo = __floats2bfloat162_rn(v.x * scale, v.y * scale);
    __nv_bfloat162 hi = __floats2bfloat162_rn(v.z * scale, v.w * scale);
    uint2 o;
    o.x = *reinterpret_cast<unsigned*>(&lo);
    o.y = *reinterpret_cast<unsigned*>(&hi);
    reinterpret_cast<uint2*>(dst)[off] = o;
}

// ---------------- y dtype detect + ticket reset ----------------
__global__ void detect_kernel(const int* __restrict__ y32) {
    if (threadIdx.x == 0) {
        int z = 0;
        for (int i = 0; i < 32; i++)
            if (y32[2 * i + 1] == 0) z++;
        g_y64 = (z >= 28) ? 1 : 0;
        g_ticket = 0;
    }
}

// ---------------- chunk loader: A (128x64) + B (128x64) bf16 ----------
__device__ __forceinline__ void load_chunk(
    uint32_t dstbase,
    const __nv_bfloat16* __restrict__ xr,
    const __nv_bfloat16* __restrict__ wp,
    int kc, int tid)
{
    #pragma unroll
    for (int j = 0; j < 4; j++) {                 // A: 1024 x 16B segs
        int idx = j * THREADS + tid;
        int row = idx >> 3, seg = idx & 7;
        uint32_t sa = dstbase + SW128((uint32_t)(row * 128 + seg * 16));
        cp_async16(sa, xr + (size_t)row * H_DIM + kc * BK + seg * 8);
    }
    #pragma unroll
    for (int j = 0; j < 4; j++) {                 // B: 1024 x 16B segs
        int idx = j * THREADS + tid;
        int row = idx >> 3, seg = idx & 7;
        uint32_t sa = dstbase + A_BYTES + SW128((uint32_t)(row * 128 + seg * 16));
        cp_async16(sa, wp + (size_t)row * H_DIM + kc * BK + seg * 8);
    }
}

// decode item -> source pointers + partial slot base
struct ItemPtrs {
    const __nv_bfloat16* xr;
    const __nv_bfloat16* wp;
    size_t pbase;               // g_part base: ((model*16+mg)*128)*512 + nt*2
};
__device__ __forceinline__ ItemPtrs decode_item(unsigned it) {
    unsigned itc = (it < NITEMS) ? it : 0u;
    unsigned nt = itc >> 5;
    unsigned rem = itc & 31u;
    unsigned model = rem >> 4;
    unsigned mg = rem & 15u;
    ItemPtrs p;
    p.xr = g_xb[model] + (size_t)(mg * BM) * H_DIM;
    p.wp = g_Wb[model] + (size_t)(nt * BN) * H_DIM;
    p.pbase = ((size_t)((model * 16 + mg) * 128)) * 512 + nt * 2;
    return p;
}

// ---------------- main fused GEMM + per-tile LSE partials -------------
__global__ void __launch_bounds__(THREADS, 2) dpo_main_kernel() {
    extern __shared__ char smem[];
    const uint32_t sb = smem_u32(smem);
    const int tid = threadIdx.x;
    const int lid = tid & 31;
    const int wid = tid >> 5;
    const int wm  = wid >> 1;       // 0..3 (M position, 32 rows each)
    const int wn  = wid & 1;        // 0..1 (N position, 64 cols each)

    const uint32_t mb_full0  = sb;          // full[b] at sb + b*8
    const uint32_t mb_empty0 = sb + 24;     // empty[b] at sb + 24 + b*8
    unsigned* sm_next = (unsigned*)(smem + 48);

    if (tid == 0) {
        #pragma unroll
        for (int b = 0; b < 3; b++) {
            MBARRIER_INIT(mb_full0  + b * 8, THREADS);
            MBARRIER_INIT(mb_empty0 + b * 8, THREADS);
        }
    }
    __syncthreads();

    // fetch two tickets
    unsigned it0, it1;
    if (tid == 0) *sm_next = atomicAdd(&g_ticket, 1u);
    __syncthreads();
    it0 = *sm_next;
    __syncthreads();
    if (tid == 0) *sm_next = atomicAdd(&g_ticket, 1u);
    __syncthreads();
    it1 = *sm_next;
    __syncthreads();

    if (it0 >= NITEMS) return;   // cannot happen for GRID < NITEMS, safe anyway

    ItemPtrs cur = decode_item(it0);
    ItemPtrs nxt = decode_item(it1);

    // swizzled base offsets (relative to buffer base)
    const int a_row0 = wm * 32 + (lid & 15);
    const uint32_t a_kh = (uint32_t)((lid >> 4) * 16);
    const int b_row0 = wn * 64 + (lid & 7) + ((lid >> 4) << 3);
    const uint32_t b_kh = (uint32_t)(((lid >> 3) & 1) * 16);

    uint32_t a_off[2], b_off[4];
    #pragma unroll
    for (int i = 0; i < 2; i++)
        a_off[i] = SW128((uint32_t)((a_row0 + i * 16) * 128) + a_kh);
    #pragma unroll
    for (int j = 0; j < 4; j++)
        b_off[j] = SW128((uint32_t)((b_row0 + j * 16) * 128) + b_kh) + A_BYTES;

    float acc[2][8][4];
    #pragma unroll
    for (int i = 0; i < 2; i++)
        #pragma unroll
        for (int j = 0; j < 8; j++)
            #pragma unroll
            for (int q = 0; q < 4; q++) acc[i][j][q] = 0.f;

    // prologue: chunks 0,1 of item 0
    load_chunk(sb + SMEM_DATA + 0 * BUF_B, cur.xr, cur.wp, 0, tid);
    cp_async_mbar_arrive(mb_full0 + 0 * 8);
    load_chunk(sb + SMEM_DATA + 1 * BUF_B, cur.xr, cur.wp, 1, tid);
    cp_async_mbar_arrive(mb_full0 + 1 * 8);

    int cc = 0;   // flat chunk counter across items
    #pragma unroll 1
    while (it0 < NITEMS) {
        #pragma unroll 1
        for (int j = 0; j < 32; j++, cc++) {
            const int b = cc % 3;
            // consume chunk cc
            MBARRIER_WAIT_PARITY(mb_full0 + b * 8, (cc / 3) & 1);
            const uint32_t bufbase = sb + SMEM_DATA + b * BUF_B;
            #pragma unroll
            for (int ks = 0; ks < 4; ks++) {
                const uint32_t kx = (uint32_t)(ks << 5);
                uint32_t a_frag[2][4], b_frag[4][4];
                ldsm_x4(a_frag[0], (bufbase + a_off[0]) ^ kx);
                ldsm_x4(a_frag[1], (bufbase + a_off[1]) ^ kx);
                #pragma unroll
                for (int j2 = 0; j2 < 4; j2++)
                    ldsm_x4(b_frag[j2], (bufbase + b_off[j2]) ^ kx);
                #pragma unroll
                for (int j2 = 0; j2 < 4; j2++)
                    #pragma unroll
                    for (int i = 0; i < 2; i++) {
                        mma16816(acc[i][j2 * 2],     a_frag[i], b_frag[j2][0], b_frag[j2][1]);
                        mma16816(acc[i][j2 * 2 + 1], a_frag[i], b_frag[j2][2], b_frag[j2][3]);
                    }
            }
            MBARRIER_ARRIVE(mb_empty0 + b * 8);

            // prefetch chunk cc+2
            const int j2c = j + 2;
            const bool nxtgrp = (j2c >= 32);
            if (!nxtgrp || it1 < NITEMS) {
                const ItemPtrs& src = nxtgrp ? nxt : cur;
                const int b2 = (cc + 2) % 3;
                if (cc >= 1)
                    MBARRIER_WAIT_PARITY(mb_empty0 + b2 * 8, ((cc - 1) / 3) & 1);
                load_chunk(sb + SMEM_DATA + b2 * BUF_B, src.xr, src.wp, j2c & 31, tid);
                cp_async_mbar_arrive(mb_full0 + b2 * 8);
            }
        }

        // epilogue: per-tile max / sum-exp2 over 128 cols; write partials
        #pragma unroll
        for (int i = 0; i < 2; i++) {
            #pragma unroll
            for (int rh = 0; rh < 2; rh++) {
                float rmax = -3.0e38f;
                #pragma unroll
                for (int j = 0; j < 8; j++)
                    rmax = fmaxf(rmax, fmaxf(acc[i][j][rh * 2],
                                             acc[i][j][rh * 2 + 1]));
                rmax = fmaxf(rmax, __shfl_xor_sync(0xffffffffu, rmax, 1));
                rmax = fmaxf(rmax, __shfl_xor_sync(0xffffffffu, rmax, 2));
                __half2 s2 = __float2half2_rn(0.f);
                #pragma unroll
                for (int j = 0; j < 8; j++) {
                    float d0 = acc[i][j][rh * 2]     - rmax;
                    float d1 = acc[i][j][rh * 2 + 1] - rmax;
                    s2 = __hadd2(s2, h2exp2(__floats2half2_rn(d0, d1)));
                }
                float2 sf = __half22float2(s2);
                float st = sf.x + sf.y;
                st += __shfl_xor_sync(0xffffffffu, st, 1);
                st += __shfl_xor_sync(0xffffffffu, st, 2);
                if ((lid & 3) == 0) {
                    int row = wm * 32 + i * 16 + rh * 8 + (lid >> 2);
                    g_part[cur.pbase + (size_t)row * 512 + wn] =
                        make_float2(rmax, st);
                }
            }
        }
        #pragma unroll
        for (int i = 0; i < 2; i++)
            #pragma unroll
            for (int j = 0; j < 8; j++)
                #pragma unroll
                for (int q = 0; q < 4; q++) acc[i][j][q] = 0.f;

        // rotate items; fetch new lookahead ticket
        it0 = it1;
        cur = nxt;
        __syncthreads();
        if (tid == 0)
            *sm_next = (it0 < NITEMS) ? atomicAdd(&g_ticket, 1u) : NITEMS;
        __syncthreads();
        it1 = *sm_next;
        nxt = decode_item(it1);
    }
}

// ---------------- combine 500 partials/row + exact fp32 token dot -----
__global__ void reduce_kernel(const void* __restrict__ yp,
                              const float* __restrict__ x,
                              const float* __restrict__ rx,
                              const float* __restrict__ W,
                              const float* __restrict__ rW) {
    int wid = threadIdx.x >> 5, lid = threadIdx.x & 31;
    int row_all = blockIdx.x * 8 + wid;        // 512 blocks -> 4096 rows
    if (row_all >= 2 * NROWS) return;
    int model = row_all >> 11;
    int r     = row_all & (NROWS - 1);
    int mg    = r >> 7;
    int localrow = r & 127;

    long long yv = g_y64 ? ((const long long*)yp)[r]
                         : (long long)((const int*)yp)[r];
    bool mask = (yv != -100);
    int safe = mask ? (int)yv : 0;

    // exact token logit from ORIGINAL fp32 inputs (natural units)
    const float4* xr = (const float4*)((model ? rx : x) + (size_t)r * H_DIM);
    const float4* wr = (const float4*)((model ? rW : W) + (size_t)safe * H_DIM);
    float acc = 0.f;
    #pragma unroll 4
    for (int t = 0; t < 16; t++) {
        int i = t * 32 + lid;
        float4 a = xr[i];
        float4 b = wr[i];
        acc = fmaf(a.x, b.x, acc);
        acc = fmaf(a.y, b.y, acc);
        acc = fmaf(a.z, b.z, acc);
        acc = fmaf(a.w, b.w, acc);
    }
    #pragma unroll
    for (int off = 16; off; off >>= 1)
        acc += __shfl_xor_sync(0xffffffffu, acc, off);

    // combine 2*NTILES = 500 (m, s) partials for this row
    const float2* pp = &g_part[((size_t)((model * 16 + mg) * 128 + localrow)) * 512];
    float M = -3.0e38f, S = 0.f;
    for (int t = 0; t < 16; t++) {
        int idx = t * 32 + lid;
        if (idx < 2 * NTILES) {
            float2 v = pp[idx];
            float mnew = fmaxf(M, v.x);
            S = S * exp2f(M - mnew) + v.y * exp2f(v.x - mnew);
            M = mnew;
        }
    }
    #pragma unroll
    for (int off = 16; off; off >>= 1) {
        float Mo = __shfl_xor_sync(0xffffffffu, M, off);
        float So = __shfl_xor_sync(0xffffffffu, S, off);
        float mnew = fmaxf(M, Mo);
        S = S * exp2f(M - mnew) + So * exp2f(Mo - mnew);
        M = mnew;
    }
    float lse_nat = LN2 * (M + log2f(S));
    if (lid == 0) {
        g_logp[row_all]  = mask ? (acc - lse_nat) : 0.f;
        g_maskf[row_all] = mask ? 1.f : 0.f;
    }
}

// ---------------- final loss ----------------
__global__ void final_kernel(float* __restrict__ out) {
    __shared__ float avg[8];
    int wid = threadIdx.x >> 5, lid = threadIdx.x & 31;
    float sl = 0.f, sm = 0.f;
    for (int i = lid; i < 512; i += 32) {
        sl += g_logp[wid * 512 + i];
        sm += g_maskf[wid * 512 + i];
    }
    #pragma unroll
    for (int off = 16; off; off >>= 1) {
        sl += __shfl_xor_sync(0xffffffffu, sl, off);
        sm += __shfl_xor_sync(0xffffffffu, sm, off);
    }
    if (lid == 0) avg[wid] = (sm > 0.f) ? (sl / sm) : 0.f;
    __syncthreads();
    if (threadIdx.x == 0) {
        const float BETA = 0.1f;
        float loss = 0.f;
        for (int b = 0; b < 4; b++) {
            float lr = avg[b] - avg[4 + b];
            float z = (b < 2) ? (BETA * lr) : (-BETA * lr);
            float sig = 1.f / (1.f + expf(-z));
            loss += 1.f - sig;
        }
        out[0] = loss / 2.f;
    }
}

// ---------------- launcher ----------------
extern "C" void kernel_launch(void* const* d_in, const int* in_sizes, int n_in,
                              void* d_out, int out_size) {
    const float* x  = (const float*)d_in[0];
    const float* rx = (const float*)d_in[1];
    const void*  y  = d_in[2];
    const float* W  = (const float*)d_in[3];
    const float* rW = (const float*)d_in[4];
    float* out = (float*)d_out;

    cudaFuncSetAttribute(dpo_main_kernel,
                         cudaFuncAttributeMaxDynamicSharedMemorySize, SMEM_TOTAL);

    const int cvt_blocks = (2 * WN4 + 2 * XN4) / 256;   // 136192 exact
    cvt_all_kernel<<<cvt_blocks, 256>>>(x, rx, W, rW);
    detect_kernel<<<1, 32>>>((const int*)y);
    dpo_main_kernel<<<GRID, THREADS, SMEM_TOTAL>>>();
    reduce_kernel<<<512, 256>>>(y, x, rx, W, rW);
    final_kernel<<<1, 256>>>(out);
}

// round 10
// speedup vs baseline: 1.3842x; 1.0174x over previous
#include <cuda_runtime.h>
#include <cuda_bf16.h>
#include <cuda_fp16.h>
#include <cstdint>
#include <cstddef>

// ---------------- problem constants ----------------
#define H_DIM   2048
#define V_DIM   32000
#define NROWS   2048            // B*T rows per model
#define BM      128
#define BN      256
#define BK      32              // fp16 elems per K chunk (64 bytes/row)
#define NTILES  125             // 32000 / 256
#define NITEMS  (NTILES * 32)   // 4000 items = (nt, model, mgroup)
#define KCH     64              // K-chunks per item (2048/32)
#define GRID    296             // 2 * 148 SMs (occ 2)
#define THREADS 256
#define PARTS   500             // partials per row = NTILES*4
#define L2E     1.4426950408889634f
#define LN2     0.6931471805599453f

// ---------------- SMEM ----------------
#define A_BYTES (BM * 64)               // 8192
#define B_BYTES (BN * 64)               // 16384
#define BUF_B   (A_BYTES + B_BYTES)     // 24576
#define SMEM_DATA 1024
#define SMEM_TOTAL (SMEM_DATA + 4 * BUF_B)   // 99328 -> 2 CTAs/SM

// ---------------- device scratch ----------------
__device__ __half g_Wh[2][(size_t)V_DIM * H_DIM];
__device__ __half g_xh[2][(size_t)NROWS * H_DIM];   // pre-scaled by log2(e)
__device__ float2   g_part[(size_t)2 * NROWS * 512];
__device__ float    g_logp[2 * NROWS];
__device__ float    g_maskf[2 * NROWS];
__device__ int      g_y64;
__device__ unsigned g_ticket;

// ---------------- helpers ----------------
__device__ __forceinline__ uint32_t smem_u32(const void* p) {
    uint32_t a;
    asm("{ .reg .u64 t; cvta.to.shared.u64 t, %1; cvt.u32.u64 %0, t; }"
        : "=r"(a) : "l"(p));
    return a;
}

#define SW64(o) ((o) ^ (((o) >> 3) & 0x30))

__device__ __forceinline__ void cp_async16(uint32_t saddr, const void* gaddr) {
    asm volatile("cp.async.cg.shared.global [%0], [%1], 16;"
                 :: "r"(saddr), "l"(gaddr) : "memory");
}

__device__ __forceinline__ void cp_async_mbar_arrive(uint32_t mbar) {
    asm volatile("cp.async.mbarrier.arrive.noinc.shared.b64 [%0];"
                 :: "r"(mbar) : "memory");
}

#define MBARRIER_INIT(addr, cnt) \
    asm volatile("mbarrier.init.shared.b64 [%0], %1;" \
        :: "r"((uint32_t)(addr)), "r"((uint32_t)(cnt)) : "memory")

#define MBARRIER_ARRIVE(addr) \
    asm volatile("mbarrier.arrive.shared.b64 _, [%0];" \
        :: "r"((uint32_t)(addr)) : "memory")

#define MBARRIER_WAIT_PARITY(addr, par) do {                                   \
    uint32_t _mb = (uint32_t)(addr); uint32_t _pp = (uint32_t)(par);           \
    uint32_t _done;                                                            \
    asm volatile("{\n\t.reg .pred p;\n\t"                                      \
        "mbarrier.try_wait.parity.acquire.cta.shared::cta.b64 p, [%1], %2;\n\t"\
        "selp.b32 %0, 1, 0, p;\n\t}"                                           \
        : "=r"(_done) : "r"(_mb), "r"(_pp) : "memory");                        \
    if (!_done) {                                                              \
        asm volatile("{\n\t.reg .pred P1;\n\t"                                 \
            "WAIT_LOOP_%=:\n\t"                                                \
            "mbarrier.try_wait.parity.acquire.cta.shared::cta.b64 P1, [%0], %1, 0x989680;\n\t" \
            "@P1 bra.uni WAIT_DONE_%=;\n\t"                                    \
            "bra.uni WAIT_LOOP_%=;\n\t"                                        \
            "WAIT_DONE_%=:\n\t}"                                               \
            :: "r"(_mb), "r"(_pp) : "memory");                                 \
    }                                                                          \
} while (0)

__device__ __forceinline__ void ldsm_x4(uint32_t (&r)[4], uint32_t addr) {
    asm volatile("ldmatrix.sync.aligned.m8n8.x4.shared.b16 {%0,%1,%2,%3}, [%4];"
        : "=r"(r[0]), "=r"(r[1]), "=r"(r[2]), "=r"(r[3]) : "r"(addr));
}

// fp16 MMA with f16 accumulators: D(16x8) += A(16x16) * B(16x8)
__device__ __forceinline__ void mma16816h(uint32_t (&d)[2], const uint32_t (&a)[4],
                                          uint32_t b0, uint32_t b1) {
    asm volatile(
        "mma.sync.aligned.m16n8k16.row.col.f16.f16.f16.f16 "
        "{%0,%1}, {%2,%3,%4,%5}, {%6,%7}, {%0,%1};"
        : "+r"(d[0]), "+r"(d[1])
        : "r"(a[0]), "r"(a[1]), "r"(a[2]), "r"(a[3]), "r"(b0), "r"(b1));
}

// ---------------- merged fp32 -> fp16 conversion -----------------------
#define WN4 (V_DIM * H_DIM / 4)     // 16,384,000
#define XN4 (NROWS * H_DIM / 4)     // 1,048,576

__global__ void cvt_all_kernel(const float* __restrict__ x,
                               const float* __restrict__ rx,
                               const float* __restrict__ W,
                               const float* __restrict__ rW) {
    int i = blockIdx.x * blockDim.x + threadIdx.x;
    const float* src;
    __half* dst;
    float scale;
    int off;
    if (i < WN4)                { src = W;  dst = g_Wh[0]; scale = 1.0f; off = i; }
    else if (i < 2 * WN4)       { src = rW; dst = g_Wh[1]; scale = 1.0f; off = i - WN4; }
    else if (i < 2 * WN4 + XN4) { src = x;  dst = g_xh[0]; scale = L2E;  off = i - 2 * WN4; }
    else                        { src = rx; dst = g_xh[1]; scale = L2E;  off = i - 2 * WN4 - XN4; }
    float4 v = reinterpret_cast<const float4*>(src)[off];
    __half2 lo = __floats2half2_rn(v.x * scale, v.y * scale);
    __half2 hi = __floats2half2_rn(v.z * scale, v.w * scale);
    uint2 o;
    o.x = *reinterpret_cast<unsigned*>(&lo);
    o.y = *reinterpret_cast<unsigned*>(&hi);
    reinterpret_cast<uint2*>(dst)[off] = o;
}

// ---------------- y dtype detect + ticket reset ----------------
__global__ void detect_kernel(const int* __restrict__ y32) {
    if (threadIdx.x == 0) {
        int z = 0;
        for (int i = 0; i < 32; i++)
            if (y32[2 * i + 1] == 0) z++;
        g_y64 = (z >= 28) ? 1 : 0;
        g_ticket = 0;
    }
}

// ---------------- chunk loader: A (128x32) + B (256x32) fp16 ----------
__device__ __forceinline__ void load_chunk(
    uint32_t dstbase,
    const __half* __restrict__ xr,
    const __half* __restrict__ wp,
    int kc, int tid)
{
    #pragma unroll
    for (int j = 0; j < 2; j++) {                 // A: 512 x 16B segs
        int idx = j * THREADS + tid;
        int row = idx >> 2, seg = idx & 3;
        uint32_t sa = dstbase + SW64((uint32_t)(row * 64 + seg * 16));
        cp_async16(sa, xr + (size_t)row * H_DIM + kc * BK + seg * 8);
    }
    #pragma unroll
    for (int j = 0; j < 4; j++) {                 // B: 1024 x 16B segs
        int idx = j * THREADS + tid;
        int row = idx >> 2, seg = idx & 3;
        uint32_t sa = dstbase + A_BYTES + SW64((uint32_t)(row * 64 + seg * 16));
        cp_async16(sa, wp + (size_t)row * H_DIM + kc * BK + seg * 8);
    }
}

// decode item -> source pointers + partial slot base
struct ItemPtrs {
    const __half* xr;
    const __half* wp;
    size_t pbase;     // g_part base: ((model*16+mg)*128)*512 + nt*4
};
__device__ __forceinline__ ItemPtrs decode_item(unsigned it) {
    unsigned itc = (it < NITEMS) ? it : 0u;
    unsigned nt = itc >> 5;
    unsigned rem = itc & 31u;
    unsigned model = rem >> 4;
    unsigned mg = rem & 15u;
    ItemPtrs p;
    p.xr = g_xh[model] + (size_t)(mg * BM) * H_DIM;
    p.wp = g_Wh[model] + (size_t)(nt * BN) * H_DIM;
    p.pbase = ((size_t)((model * 16 + mg) * 128)) * 512 + nt * 4;
    return p;
}

// ---------------- main fused GEMM (f16 acc) + per-tile LSE ------------
__global__ void __launch_bounds__(THREADS, 2) dpo_main_kernel() {
    extern __shared__ char smem[];
    const uint32_t sb = smem_u32(smem);
    const int tid = threadIdx.x;
    const int lid = tid & 31;
    const int wid = tid >> 5;
    const int wm  = wid >> 2;       // 0..1 (M position, 64 rows each)
    const int wn  = wid & 3;        // 0..3 (N position, 64 cols each)

    const uint32_t mb_full0  = sb;          // full[b] at sb + b*8
    const uint32_t mb_empty0 = sb + 32;     // empty[b] at sb + 32 + b*8
    unsigned* sm_next = (unsigned*)(smem + 64);

    if (tid == 0) {
        #pragma unroll
        for (int b = 0; b < 4; b++) {
            MBARRIER_INIT(mb_full0  + b * 8, THREADS);
            MBARRIER_INIT(mb_empty0 + b * 8, THREADS);
        }
    }
    __syncthreads();

    // fetch two tickets
    unsigned it0, it1;
    if (tid == 0) *sm_next = atomicAdd(&g_ticket, 1u);
    __syncthreads();
    it0 = *sm_next;
    __syncthreads();
    if (tid == 0) *sm_next = atomicAdd(&g_ticket, 1u);
    __syncthreads();
    it1 = *sm_next;
    __syncthreads();

    if (it0 >= NITEMS) return;

    ItemPtrs cur = decode_item(it0);
    ItemPtrs nxt = decode_item(it1);

    // swizzled base offsets (relative to buffer base)
    const int a_row0 = wm * 64 + (lid & 15);
    const uint32_t a_kh = (uint32_t)((lid >> 4) * 16);
    const int b_row0 = wn * 64 + (lid & 7) + ((lid >> 4) << 3);
    const uint32_t b_kh = (uint32_t)(((lid >> 3) & 1) * 16);

    uint32_t a_off[4], b_off[4];
    #pragma unroll
    for (int i = 0; i < 4; i++)
        a_off[i] = SW64((uint32_t)((a_row0 + i * 16) * 64) + a_kh);
    #pragma unroll
    for (int j = 0; j < 4; j++)
        b_off[j] = SW64((uint32_t)((b_row0 + j * 16) * 64) + b_kh) + A_BYTES;

    uint32_t acc[4][8][2];   // f16x2 accumulators, warp tile 64x64
    #pragma unroll
    for (int i = 0; i < 4; i++)
        #pragma unroll
        for (int j = 0; j < 8; j++)
            { acc[i][j][0] = 0u; acc[i][j][1] = 0u; }

    // prologue: chunks 0,1,2 into buffers 0,1,2
    #pragma unroll
    for (int c = 0; c < 3; c++) {
        load_chunk(sb + SMEM_DATA + c * BUF_B, cur.xr, cur.wp, c, tid);
        cp_async_mbar_arrive(mb_full0 + c * 8);
    }

    int cc = 0;   // flat chunk counter across items
    #pragma unroll 1
    while (it0 < NITEMS) {
        #pragma unroll 1
        for (int j = 0; j < KCH; j++, cc++) {
            const int b = cc & 3;
            MBARRIER_WAIT_PARITY(mb_full0 + b * 8, (cc >> 2) & 1);

            const uint32_t bufbase = sb + SMEM_DATA + b * BUF_B;
            #pragma unroll
            for (int ks = 0; ks < 2; ks++) {
                const uint32_t kx = (uint32_t)(ks << 5);
                uint32_t a_frag[4][4], b_frag[4][4];
                #pragma unroll
                for (int i = 0; i < 4; i++)
                    ldsm_x4(a_frag[i], (bufbase + a_off[i]) ^ kx);
                #pragma unroll
                for (int j2 = 0; j2 < 4; j2++)
                    ldsm_x4(b_frag[j2], (bufbase + b_off[j2]) ^ kx);
                #pragma unroll
                for (int j2 = 0; j2 < 4; j2++)
                    #pragma unroll
                    for (int i = 0; i < 4; i++) {
                        mma16816h(acc[i][j2 * 2],     a_frag[i], b_frag[j2][0], b_frag[j2][1]);
                        mma16816h(acc[i][j2 * 2 + 1], a_frag[i], b_frag[j2][2], b_frag[j2][3]);
                    }
            }
            MBARRIER_ARRIVE(mb_empty0 + b * 8);

            // prefetch chunk cc+3
            const int j3 = j + 3;
            const bool nxtgrp = (j3 >= KCH);
            if (!nxtgrp || it1 < NITEMS) {
                const ItemPtrs& src = nxtgrp ? nxt : cur;
                const int cp = cc + 3;
                const int b2 = cp & 3;
                if (cp >= 4)
                    MBARRIER_WAIT_PARITY(mb_empty0 + b2 * 8, ((cp - 4) >> 2) & 1);
                load_chunk(sb + SMEM_DATA + b2 * BUF_B, src.xr, src.wp, j3 & (KCH - 1), tid);
                cp_async_mbar_arrive(mb_full0 + b2 * 8);
            }
        }

        // epilogue: per-tile max / sum-exp2 over this warp's 64 cols
        #pragma unroll
        for (int i = 0; i < 4; i++) {
            #pragma unroll
            for (int rh = 0; rh < 2; rh++) {
                __half2 m2 = __floats2half2_rn(-60000.f, -60000.f);
                #pragma unroll
                for (int j = 0; j < 8; j++) {
                    __half2 v = *reinterpret_cast<__half2*>(&acc[i][j][rh]);
                    m2 = __hmax2(m2, v);
                }
                float2 mf = __half22float2(m2);
                float rmax = fmaxf(mf.x, mf.y);
                rmax = fmaxf(rmax, __shfl_xor_sync(0xffffffffu, rmax, 1));
                rmax = fmaxf(rmax, __shfl_xor_sync(0xffffffffu, rmax, 2));
                __half2 rm2 = __float2half2_rn(rmax);
                __half2 s2 = __float2half2_rn(0.f);
                #pragma unroll
                for (int j = 0; j < 8; j++) {
                    __half2 v = *reinterpret_cast<__half2*>(&acc[i][j][rh]);
                    s2 = __hadd2(s2, h2exp2(__hsub2(v, rm2)));
                }
                float2 sf = __half22float2(s2);
                float st = sf.x + sf.y;
                st += __shfl_xor_sync(0xffffffffu, st, 1);
                st += __shfl_xor_sync(0xffffffffu, st, 2);
                if ((lid & 3) == 0) {
                    int row = wm * 64 + i * 16 + rh * 8 + (lid >> 2);
                    g_part[cur.pbase + (size_t)row * 512 + wn] =
                        make_float2(rmax, st);
                }
            }
        }
        #pragma unroll
        for (int i = 0; i < 4; i++)
            #pragma unroll
            for (int j = 0; j < 8; j++)
                { acc[i][j][0] = 0u; acc[i][j][1] = 0u; }

        // rotate items; fetch new lookahead ticket
        it0 = it1;
        cur = nxt;
        __syncthreads();
        if (tid == 0)
            *sm_next = (it0 < NITEMS) ? atomicAdd(&g_ticket, 1u) : NITEMS;
        __syncthreads();
        it1 = *sm_next;
        nxt = decode_item(it1);
    }
}

// ---------------- combine 500 partials/row + exact fp32 token dot -----
__global__ void reduce_kernel(const void* __restrict__ yp,
                              const float* __restrict__ x,
                              const float* __restrict__ rx,
                              const float* __restrict__ W,
                              const float* __restrict__ rW) {
    int wid = threadIdx.x >> 5, lid = threadIdx.x & 31;
    int row_all = blockIdx.x * 8 + wid;        // 512 blocks -> 4096 rows
    if (row_all >= 2 * NROWS) return;
    int model = row_all >> 11;
    int r     = row_all & (NROWS - 1);
    int mg    = r >> 7;
    int localrow = r & 127;

    long long yv = g_y64 ? ((const long long*)yp)[r]
                         : (long long)((const int*)yp)[r];
    bool mask = (yv != -100);
    int safe = mask ? (int)yv : 0;

    // exact token logit from ORIGINAL fp32 inputs (natural units)
    const float4* xr = (const float4*)((model ? rx : x) + (size_t)r * H_DIM);
    const float4* wr = (const float4*)((model ? rW : W) + (size_t)safe * H_DIM);
    float acc = 0.f;
    #pragma unroll 4
    for (int t = 0; t < 16; t++) {
        int i = t * 32 + lid;
        float4 a = xr[i];
        float4 b = wr[i];
        acc = fmaf(a.x, b.x, acc);
        acc = fmaf(a.y, b.y, acc);
        acc = fmaf(a.z, b.z, acc);
        acc = fmaf(a.w, b.w, acc);
    }
    #pragma unroll
    for (int off = 16; off; off >>= 1)
        acc += __shfl_xor_sync(0xffffffffu, acc, off);

    // combine PARTS = 500 (m, s) partials for this row
    const float2* pp = &g_part[((size_t)((model * 16 + mg) * 128 + localrow)) * 512];
    float M = -3.0e38f, S = 0.f;
    for (int t = 0; t < 16; t++) {
        int idx = t * 32 + lid;
        if (idx < PARTS) {
            float2 v = pp[idx];
            float mnew = fmaxf(M, v.x);
            S = S * exp2f(M - mnew) + v.y * exp2f(v.x - mnew);
            M = mnew;
        }
    }
    #pragma unroll
    for (int off = 16; off; off >>= 1) {
        float Mo = __shfl_xor_sync(0xffffffffu, M, off);
        float So = __shfl_xor_sync(0xffffffffu, S, off);
        float mnew = fmaxf(M, Mo);
        S = S * exp2f(M - mnew) + So * exp2f(Mo - mnew);
        M = mnew;
    }
    float lse_nat = LN2 * (M + log2f(S));
    if (lid == 0) {
        g_logp[row_all]  = mask ? (acc - lse_nat) : 0.f;
        g_maskf[row_all] = mask ? 1.f : 0.f;
    }
}

// ---------------- final loss ----------------
__global__ void final_kernel(float* __restrict__ out) {
    __shared__ float avg[8];
    int wid = threadIdx.x >> 5, lid = threadIdx.x & 31;
    float sl = 0.f, sm = 0.f;
    for (int i = lid; i < 512; i += 32) {
        sl += g_logp[wid * 512 + i];
        sm += g_maskf[wid * 512 + i];
    }
    #pragma unroll
    for (int off = 16; off; off >>= 1) {
        sl += __shfl_xor_sync(0xffffffffu, sl, off);
        sm += __shfl_xor_sync(0xffffffffu, sm, off);
    }
    if (lid == 0) avg[wid] = (sm > 0.f) ? (sl / sm) : 0.f;
    __syncthreads();
    if (threadIdx.x == 0) {
        const float BETA = 0.1f;
        float loss = 0.f;
        for (int b = 0; b < 4; b++) {
            float lr = avg[b] - avg[4 + b];
            float z = (b < 2) ? (BETA * lr) : (-BETA * lr);
            float sig = 1.f / (1.f + expf(-z));
            loss += 1.f - sig;
        }
        out[0] = loss / 2.f;
    }
}

// ---------------- launcher ----------------
extern "C" void kernel_launch(void* const* d_in, const int* in_sizes, int n_in,
                              void* d_out, int out_size) {
    const float* x  = (const float*)d_in[0];
    const float* rx = (const float*)d_in[1];
    const void*  y  = d_in[2];
    const float* W  = (const float*)d_in[3];
    const float* rW = (const float*)d_in[4];
    float* out = (float*)d_out;

    cudaFuncSetAttribute(dpo_main_kernel,
                         cudaFuncAttributeMaxDynamicSharedMemorySize, SMEM_TOTAL);

    const int cvt_blocks = (2 * WN4 + 2 * XN4) / 256;   // exact
    cvt_all_kernel<<<cvt_blocks, 256>>>(x, rx, W, rW);
    detect_kernel<<<1, 32>>>((const int*)y);
    dpo_main_kernel<<<GRID, THREADS, SMEM_TOTAL>>>();
    reduce_kernel<<<512, 256>>>(y, x, rx, W, rW);
    final_kernel<<<1, 256>>>(out);
}